// round 7
// baseline (speedup 1.0000x reference)
#include <cuda_runtime.h>
#include <math.h>
#include <stdint.h>

#define DIMV   1024
#define DEPTH  4
#define HEADS  16
#define DHEAD  64
#define INNER  1024
#define MLPV   4096
#define BATCH  2
#define SEQ    1024
#define ROWS   (BATCH*SEQ)

// ---------------- scratch (no allocations allowed; __device__ globals) -------
__device__ float g_ln  [ROWS * DIMV];        // LN output           (8 MB)
__device__ float g_qkv [ROWS * 3 * INNER];   // qkv projection      (24 MB)
__device__ float g_attn[ROWS * INNER];       // attention output    (8 MB)
__device__ float g_ffh [ROWS * MLPV];        // ff hidden           (32 MB)
__device__ float g_x   [ROWS * DIMV];        // running residual x  (8 MB)

// ---------------- LayerNorm --------------------------------------------------
__global__ void ln_kernel(const float* __restrict__ x,
                          const float* __restrict__ g,
                          const float* __restrict__ b,
                          float* __restrict__ out)
{
    __shared__ float red[8];
    __shared__ float sh_mu, sh_rs;
    const int row = blockIdx.x;
    const int tid = threadIdx.x;          // 256 threads, 4 elems each
    float4 v = ((const float4*)(x + (size_t)row * DIMV))[tid];

    float s = (v.x + v.y) + (v.z + v.w);
    #pragma unroll
    for (int o = 16; o; o >>= 1) s += __shfl_xor_sync(0xffffffffu, s, o);
    if ((tid & 31) == 0) red[tid >> 5] = s;
    __syncthreads();
    if (tid == 0) {
        float t = red[0];
        #pragma unroll
        for (int i = 1; i < 8; i++) t += red[i];
        sh_mu = t * (1.0f / DIMV);
    }
    __syncthreads();
    const float mu = sh_mu;
    float d0 = v.x - mu, d1 = v.y - mu, d2 = v.z - mu, d3 = v.w - mu;
    s = d0*d0 + d1*d1 + d2*d2 + d3*d3;
    #pragma unroll
    for (int o = 16; o; o >>= 1) s += __shfl_xor_sync(0xffffffffu, s, o);
    if ((tid & 31) == 0) red[tid >> 5] = s;
    __syncthreads();
    if (tid == 0) {
        float t = red[0];
        #pragma unroll
        for (int i = 1; i < 8; i++) t += red[i];
        sh_rs = rsqrtf(t * (1.0f / DIMV) + 1e-5f);
    }
    __syncthreads();
    const float rs = sh_rs;
    float4 gg = ((const float4*)g)[tid];
    float4 bb = ((const float4*)b)[tid];
    float4 r;
    r.x = d0 * rs * gg.x + bb.x;
    r.y = d1 * rs * gg.y + bb.y;
    r.z = d2 * rs * gg.z + bb.z;
    r.w = d3 * rs * gg.w + bb.w;
    ((float4*)(out + (size_t)row * DIMV))[tid] = r;
}

// ---------------- SGEMM: C[M,N] = A[M,K] @ B[K,N] (+epilogue) ---------------
// EPI: 0 = none, 1 = +bias +residual, 2 = +bias +exact GELU
__device__ __forceinline__ float gelu_exact(float x)
{
    return 0.5f * x * (1.0f + erff(x * 0.70710678118654752f));
}

template <int EPI>
__global__ void __launch_bounds__(256, 2)
sgemm_kernel(const float* __restrict__ A, const float* __restrict__ Bm,
             float* __restrict__ C, const float* __restrict__ bias,
             const float* __restrict__ res, int M, int N, int K)
{
    __shared__ __align__(16) float As[8][128];
    __shared__ __align__(16) float Bs[8][128];

    const int tid  = threadIdx.x;
    const int tx   = tid & 15;
    const int ty   = tid >> 4;
    const int brow = blockIdx.y * 128;
    const int bcol = blockIdx.x * 128;

    const int arow  = tid >> 1;          // 0..127
    const int acol  = (tid & 1) * 4;     // 0 or 4
    const int brow8 = tid >> 5;          // 0..7
    const int bcol4 = (tid & 31) * 4;    // 0..124

    const float* Aptr = A  + (size_t)(brow + arow) * K + acol;
    const float* Bptr = Bm + (size_t)brow8 * N + bcol + bcol4;

    float acc[8][8];
    #pragma unroll
    for (int i = 0; i < 8; i++)
        #pragma unroll
        for (int j = 0; j < 8; j++) acc[i][j] = 0.0f;

    const int nkt = K >> 3;
    float4 an = *(const float4*)(Aptr);
    float4 bn = *(const float4*)(Bptr);

    for (int kt = 0; kt < nkt; kt++) {
        As[acol + 0][arow] = an.x;
        As[acol + 1][arow] = an.y;
        As[acol + 2][arow] = an.z;
        As[acol + 3][arow] = an.w;
        *(float4*)&Bs[brow8][bcol4] = bn;
        __syncthreads();

        if (kt + 1 < nkt) {
            an = *(const float4*)(Aptr + (kt + 1) * 8);
            bn = *(const float4*)(Bptr + (size_t)(kt + 1) * 8 * N);
        }

        #pragma unroll
        for (int k = 0; k < 8; k++) {
            float av[8], bv[8];
            *(float4*)&av[0] = *(const float4*)&As[k][ty * 4];
            *(float4*)&av[4] = *(const float4*)&As[k][64 + ty * 4];
            *(float4*)&bv[0] = *(const float4*)&Bs[k][tx * 4];
            *(float4*)&bv[4] = *(const float4*)&Bs[k][64 + tx * 4];
            #pragma unroll
            for (int i = 0; i < 8; i++)
                #pragma unroll
                for (int j = 0; j < 8; j++)
                    acc[i][j] += av[i] * bv[j];
        }
        __syncthreads();
    }

    // epilogue
    #pragma unroll
    for (int i = 0; i < 8; i++) {
        const int row = brow + ((i < 4) ? (ty * 4 + i) : (64 + ty * 4 + i - 4));
        #pragma unroll
        for (int jj = 0; jj < 2; jj++) {
            const int col = bcol + (jj ? (64 + tx * 4) : (tx * 4));
            float4 r;
            r.x = acc[i][jj * 4 + 0];
            r.y = acc[i][jj * 4 + 1];
            r.z = acc[i][jj * 4 + 2];
            r.w = acc[i][jj * 4 + 3];
            if (EPI == 1) {
                float4 bb = *(const float4*)(bias + col);
                float4 rr = *(const float4*)(res + (size_t)row * N + col);
                r.x += bb.x + rr.x; r.y += bb.y + rr.y;
                r.z += bb.z + rr.z; r.w += bb.w + rr.w;
            } else if (EPI == 2) {
                float4 bb = *(const float4*)(bias + col);
                r.x = gelu_exact(r.x + bb.x);
                r.y = gelu_exact(r.y + bb.y);
                r.z = gelu_exact(r.z + bb.z);
                r.w = gelu_exact(r.w + bb.w);
            }
            *(float4*)(C + (size_t)row * N + col) = r;
        }
    }
}

// ---------------- Flash attention (fp32, online softmax) --------------------
// qkv layout: [B*SEQ, 3*INNER]; q at col h*64, k at INNER+h*64, v at 2*INNER+h*64.
// grid: (SEQ/128, B*HEADS), block 128; one thread per query row.
__global__ void __launch_bounds__(128)
flash_kernel(const float* __restrict__ qkv, const int* __restrict__ mask,
             float* __restrict__ outp)
{
    __shared__ __align__(16) float Ks[64][64];
    __shared__ __align__(16) float Vs[64][64];
    __shared__ unsigned char   Ms[128][68];   // padded pitch: conflict-free

    const int bh = blockIdx.y;
    const int b  = bh >> 4;
    const int h  = bh & 15;
    const int q0 = blockIdx.x * 128;
    const int tid = threadIdx.x;
    const int qrow = q0 + tid;
    const float scale = 0.125f;               // DHEAD^-0.5

    float q[64];
    const float* qp = qkv + (size_t)(b * SEQ + qrow) * (3 * INNER) + h * DHEAD;
    #pragma unroll
    for (int d = 0; d < 64; d += 4) {
        float4 t = *(const float4*)(qp + d);
        q[d] = t.x * scale; q[d+1] = t.y * scale;
        q[d+2] = t.z * scale; q[d+3] = t.w * scale;
    }

    float o[64];
    #pragma unroll
    for (int d = 0; d < 64; d++) o[d] = 0.0f;
    float m = -INFINITY, l = 0.0f;

    const int* mrow = mask + ((size_t)b * SEQ + qrow) * SEQ;

    for (int kt = 0; kt < SEQ; kt += 64) {
        // load K/V tiles (64x64 each), 128 threads x 32 floats per tile
        {
            const int r = tid >> 1;
            const int c = (tid & 1) * 32;
            const float* kp = qkv + (size_t)(b * SEQ + kt + r) * (3 * INNER)
                              + INNER + h * DHEAD + c;
            const float* vp = kp + INNER;
            #pragma unroll
            for (int j = 0; j < 32; j += 4) {
                *(float4*)&Ks[r][c + j] = *(const float4*)(kp + j);
                *(float4*)&Vs[r][c + j] = *(const float4*)(vp + j);
            }
        }
        // mask tile: this thread's own query row, 64 keys
        {
            const int* mp = mrow + kt;
            #pragma unroll
            for (int j = 0; j < 64; j += 4) {
                int4 mm = *(const int4*)(mp + j);
                Ms[tid][j]     = (unsigned char)mm.x;
                Ms[tid][j + 1] = (unsigned char)mm.y;
                Ms[tid][j + 2] = (unsigned char)mm.z;
                Ms[tid][j + 3] = (unsigned char)mm.w;
            }
        }
        __syncthreads();

        #pragma unroll 1
        for (int kk = 0; kk < 64; kk++) {
            float s0 = 0.f, s1 = 0.f, s2 = 0.f, s3 = 0.f;
            #pragma unroll
            for (int d = 0; d < 64; d += 4) {
                float4 kv = *(const float4*)&Ks[kk][d];
                s0 += q[d]     * kv.x;
                s1 += q[d + 1] * kv.y;
                s2 += q[d + 2] * kv.z;
                s3 += q[d + 3] * kv.w;
            }
            float s = (s0 + s1) + (s2 + s3);
            if (Ms[tid][kk] == 0) s = -1e9f;

            float p;
            if (s > m) {
                float c = __expf(m - s);       // expf(-inf)=0 handles init
                l *= c;
                #pragma unroll
                for (int d = 0; d < 64; d++) o[d] *= c;
                m = s;
                p = 1.0f;
            } else {
                p = __expf(s - m);
            }
            l += p;
            #pragma unroll
            for (int d = 0; d < 64; d += 4) {
                float4 vv = *(const float4*)&Vs[kk][d];
                o[d]     += p * vv.x;
                o[d + 1] += p * vv.y;
                o[d + 2] += p * vv.z;
                o[d + 3] += p * vv.w;
            }
        }
        __syncthreads();
    }

    const float inv = 1.0f / l;
    float* op = outp + (size_t)(b * SEQ + qrow) * INNER + h * DHEAD;
    #pragma unroll
    for (int d = 0; d < 64; d += 4) {
        float4 t;
        t.x = o[d] * inv;     t.y = o[d + 1] * inv;
        t.z = o[d + 2] * inv; t.w = o[d + 3] * inv;
        *(float4*)(op + d) = t;
    }
}

// ---------------- host orchestration ----------------------------------------
extern "C" void kernel_launch(void* const* d_in, const int* in_sizes, int n_in,
                              void* d_out, int out_size)
{
    (void)in_sizes; (void)n_in; (void)out_size;
    const float* x_in  = (const float*)d_in[0];
    const int*   mask  = (const int*)  d_in[1];
    const float* ln1_g = (const float*)d_in[2];
    const float* ln1_b = (const float*)d_in[3];
    const float* qkv_w = (const float*)d_in[4];
    const float* out_w = (const float*)d_in[5];
    const float* out_b = (const float*)d_in[6];
    const float* ln2_g = (const float*)d_in[7];
    const float* ln2_b = (const float*)d_in[8];
    const float* ff1_w = (const float*)d_in[9];
    const float* ff1_b = (const float*)d_in[10];
    const float* ff2_w = (const float*)d_in[11];
    const float* ff2_b = (const float*)d_in[12];

    float *p_ln, *p_qkv, *p_attn, *p_ffh, *p_x;
    cudaGetSymbolAddress((void**)&p_ln,   g_ln);
    cudaGetSymbolAddress((void**)&p_qkv,  g_qkv);
    cudaGetSymbolAddress((void**)&p_attn, g_attn);
    cudaGetSymbolAddress((void**)&p_ffh,  g_ffh);
    cudaGetSymbolAddress((void**)&p_x,    g_x);

    for (int l = 0; l < DEPTH; l++) {
        const float* xsrc = (l == 0) ? x_in : p_x;

        // h = LN1(x)
        ln_kernel<<<ROWS, 256>>>(xsrc, ln1_g + l * DIMV, ln1_b + l * DIMV, p_ln);

        // qkv = h @ qkv_w[l]
        sgemm_kernel<0><<<dim3(3 * INNER / 128, ROWS / 128), 256>>>(
            p_ln, qkv_w + (size_t)l * DIMV * 3 * INNER, p_qkv,
            nullptr, nullptr, ROWS, 3 * INNER, DIMV);

        // o = attention(q, k, v, mask)
        flash_kernel<<<dim3(SEQ / 128, BATCH * HEADS), 128>>>(p_qkv, mask, p_attn);

        // x = o @ out_w[l] + out_b[l] + x
        sgemm_kernel<1><<<dim3(DIMV / 128, ROWS / 128), 256>>>(
            p_attn, out_w + (size_t)l * INNER * DIMV, p_x,
            out_b + l * DIMV, xsrc, ROWS, DIMV, INNER);

        // h = LN2(x)
        ln_kernel<<<ROWS, 256>>>(p_x, ln2_g + l * DIMV, ln2_b + l * DIMV, p_ln);

        // ffh = gelu(h @ ff1_w[l] + ff1_b[l])
        sgemm_kernel<2><<<dim3(MLPV / 128, ROWS / 128), 256>>>(
            p_ln, ff1_w + (size_t)l * DIMV * MLPV, p_ffh,
            ff1_b + l * MLPV, nullptr, ROWS, MLPV, DIMV);

        // x = ffh @ ff2_w[l] + ff2_b[l] + x   (last layer writes d_out)
        float* xdst = (l == DEPTH - 1) ? (float*)d_out : p_x;
        sgemm_kernel<1><<<dim3(DIMV / 128, ROWS / 128), 256>>>(
            p_ffh, ff2_w + (size_t)l * MLPV * DIMV, xdst,
            ff2_b + l * DIMV, p_x, ROWS, DIMV, MLPV);
    }
}

// round 9
// speedup vs baseline: 1.4021x; 1.4021x over previous
#include <cuda_runtime.h>
#include <cuda_bf16.h>
#include <math.h>
#include <stdint.h>

#define DIMV   1024
#define DEPTH  4
#define HEADS  16
#define DHEAD  64
#define INNER  1024
#define MLPV   4096
#define BATCH  2
#define SEQ    1024
#define ROWS   (BATCH*SEQ)

// ---------------- scratch (no allocations allowed; __device__ globals) -------
__device__ float g_qkv[ROWS * 3 * INNER];            // qkv projection (fp32, 24MB)
__device__ float g_x  [ROWS * DIMV];                 // residual stream (8MB)
__device__ __nv_bfloat16 g_ah[ROWS * DIMV];          // activation split hi
__device__ __nv_bfloat16 g_al[ROWS * DIMV];          // activation split lo
__device__ __nv_bfloat16 g_fh[ROWS * MLPV];          // ff hidden split hi
__device__ __nv_bfloat16 g_fl[ROWS * MLPV];          // ff hidden split lo
// transposed + split weights  [N][K] bf16
__device__ __nv_bfloat16 w_qkv_h[DEPTH * 3*INNER * DIMV];
__device__ __nv_bfloat16 w_qkv_l[DEPTH * 3*INNER * DIMV];
__device__ __nv_bfloat16 w_out_h[DEPTH * DIMV * INNER];
__device__ __nv_bfloat16 w_out_l[DEPTH * DIMV * INNER];
__device__ __nv_bfloat16 w_ff1_h[DEPTH * MLPV * DIMV];
__device__ __nv_bfloat16 w_ff1_l[DEPTH * MLPV * DIMV];
__device__ __nv_bfloat16 w_ff2_h[DEPTH * DIMV * MLPV];
__device__ __nv_bfloat16 w_ff2_l[DEPTH * DIMV * MLPV];

// ---------------- small helpers ---------------------------------------------
__device__ __forceinline__ void bf16_split(float v, unsigned short& h, unsigned short& l)
{
    __nv_bfloat16 hb = __float2bfloat16(v);
    __nv_bfloat16 lb = __float2bfloat16(v - __bfloat162float(hb));
    h = __bfloat16_as_ushort(hb);
    l = __bfloat16_as_ushort(lb);
}

__device__ __forceinline__ float gelu_exact(float x)
{
    return 0.5f * x * (1.0f + erff(x * 0.70710678118654752f));
}

__device__ __forceinline__ uint32_t smem_u32(const void* p)
{
    uint32_t r;
    asm("{ .reg .u64 t; cvta.to.shared.u64 t, %1; cvt.u32.u64 %0, t; }"
        : "=r"(r) : "l"(p));
    return r;
}

// ---------------- mma.sync / ldmatrix / cp.async wrappers (sm_80+ PTX) -------
__device__ __forceinline__ void ldsm4(uint32_t* r, uint32_t addr)
{
    asm volatile("ldmatrix.sync.aligned.m8n8.x4.shared.b16 {%0,%1,%2,%3}, [%4];"
        : "=r"(r[0]), "=r"(r[1]), "=r"(r[2]), "=r"(r[3]) : "r"(addr));
}

__device__ __forceinline__ void mma16816(float* d, const uint32_t* a, const uint32_t* b)
{
    asm volatile(
        "mma.sync.aligned.m16n8k16.row.col.f32.bf16.bf16.f32 "
        "{%0,%1,%2,%3}, {%4,%5,%6,%7}, {%8,%9}, {%0,%1,%2,%3};"
        : "+f"(d[0]), "+f"(d[1]), "+f"(d[2]), "+f"(d[3])
        : "r"(a[0]), "r"(a[1]), "r"(a[2]), "r"(a[3]), "r"(b[0]), "r"(b[1]));
}

#define CP_ASYNC16(dst, src) \
    asm volatile("cp.async.cg.shared.global [%0], [%1], 16;" :: "r"(dst), "l"(src))
#define CP_COMMIT() asm volatile("cp.async.commit_group;" ::: "memory")
#define CP_WAIT1()  asm volatile("cp.async.wait_group 1;" ::: "memory")
#define CP_WAIT0()  asm volatile("cp.async.wait_group 0;" ::: "memory")

// ---------------- LayerNorm -> bf16 split ------------------------------------
__global__ void ln_kernel(const float* __restrict__ x,
                          const float* __restrict__ g,
                          const float* __restrict__ b,
                          unsigned short* __restrict__ oh,
                          unsigned short* __restrict__ ol)
{
    __shared__ float red[8];
    __shared__ float sh_mu, sh_rs;
    const int row = blockIdx.x;
    const int tid = threadIdx.x;          // 256 threads, 4 elems each
    float4 v = ((const float4*)(x + (size_t)row * DIMV))[tid];

    float s = (v.x + v.y) + (v.z + v.w);
    #pragma unroll
    for (int o = 16; o; o >>= 1) s += __shfl_xor_sync(0xffffffffu, s, o);
    if ((tid & 31) == 0) red[tid >> 5] = s;
    __syncthreads();
    if (tid == 0) {
        float t = red[0];
        #pragma unroll
        for (int i = 1; i < 8; i++) t += red[i];
        sh_mu = t * (1.0f / DIMV);
    }
    __syncthreads();
    const float mu = sh_mu;
    float d0 = v.x - mu, d1 = v.y - mu, d2 = v.z - mu, d3 = v.w - mu;
    s = d0*d0 + d1*d1 + d2*d2 + d3*d3;
    #pragma unroll
    for (int o = 16; o; o >>= 1) s += __shfl_xor_sync(0xffffffffu, s, o);
    if ((tid & 31) == 0) red[tid >> 5] = s;
    __syncthreads();
    if (tid == 0) {
        float t = red[0];
        #pragma unroll
        for (int i = 1; i < 8; i++) t += red[i];
        sh_rs = rsqrtf(t * (1.0f / DIMV) + 1e-5f);
    }
    __syncthreads();
    const float rs = sh_rs;
    float4 gg = ((const float4*)g)[tid];
    float4 bb = ((const float4*)b)[tid];
    float r0 = d0 * rs * gg.x + bb.x;
    float r1 = d1 * rs * gg.y + bb.y;
    float r2 = d2 * rs * gg.z + bb.z;
    float r3 = d3 * rs * gg.w + bb.w;
    unsigned short h0,h1,h2,h3,l0,l1,l2,l3;
    bf16_split(r0,h0,l0); bf16_split(r1,h1,l1);
    bf16_split(r2,h2,l2); bf16_split(r3,h3,l3);
    uint2 H, L;
    H.x = (uint32_t)h0 | ((uint32_t)h1 << 16);
    H.y = (uint32_t)h2 | ((uint32_t)h3 << 16);
    L.x = (uint32_t)l0 | ((uint32_t)l1 << 16);
    L.y = (uint32_t)l2 | ((uint32_t)l3 << 16);
    ((uint2*)(oh + (size_t)row * DIMV))[tid] = H;
    ((uint2*)(ol + (size_t)row * DIMV))[tid] = L;
}

// ---------------- weight transpose + bf16 split ------------------------------
// W [K][N] fp32 row-major -> Wh/Wl [N][K] bf16
__global__ void wconv_kernel(const float* __restrict__ W,
                             __nv_bfloat16* __restrict__ Wh,
                             __nv_bfloat16* __restrict__ Wl, int K, int N)
{
    __shared__ float t[32][33];
    const int tx = threadIdx.x, ty = threadIdx.y;   // block (32, 8)
    const int k0 = blockIdx.y * 32, n0 = blockIdx.x * 32;
    #pragma unroll
    for (int j = 0; j < 4; j++)
        t[ty + j*8][tx] = W[(size_t)(k0 + ty + j*8) * N + n0 + tx];
    __syncthreads();
    #pragma unroll
    for (int j = 0; j < 4; j++) {
        float v = t[tx][ty + j*8];
        __nv_bfloat16 hb = __float2bfloat16(v);
        __nv_bfloat16 lb = __float2bfloat16(v - __bfloat162float(hb));
        size_t o = (size_t)(n0 + ty + j*8) * K + k0 + tx;
        Wh[o] = hb; Wl[o] = lb;
    }
}

// ---------------- mma.sync GEMM: C[M,N] = (Ah+Al)[M,K] @ (Bh+Bl)[N,K]^T ------
// 3-term bf16 split: Ah*Bh + Ah*Bl + Al*Bh.
// CTA tile 128x128, 8 warps (warp tile 64x32), K-chunk 32, cp.async 2 stages.
// EPI: 0 = plain fp32, 1 = +bias +residual fp32, 2 = +bias +GELU -> bf16 hi/lo
#define PITCH    40                    // bf16 elems per smem row (80B, LDSM conflict-free)
#define TILE_B   (128 * PITCH * 2)     // 10240 B per tile
#define STAGE_B  (4 * TILE_B)          // Ah, Al, Bh, Bl
#define GSMEM_B  (2 * STAGE_B)         // 81920 B

template <int EPI>
__global__ void __launch_bounds__(256, 1)
mma_gemm(const __nv_bfloat16* __restrict__ Ah, const __nv_bfloat16* __restrict__ Al,
         const __nv_bfloat16* __restrict__ Bh, const __nv_bfloat16* __restrict__ Bl,
         float* __restrict__ C, const float* __restrict__ bias,
         const float* __restrict__ res,
         unsigned short* __restrict__ Ch, unsigned short* __restrict__ Cl,
         int N, int K)
{
    extern __shared__ __align__(128) char smem[];
    const uint32_t sb = smem_u32(smem);
    const int tid  = threadIdx.x;
    const int wid  = tid >> 5, lane = tid & 31;
    const int brow = blockIdx.y * 128, bcol = blockIdx.x * 128;

    // ---- producer mapping: row = tid/2, two 16B pieces each ----
    const int prow = tid >> 1;
    const int pp   = (tid & 1) * 2;          // pieces pp, pp+1 (of 4 per 64B row)
    const size_t kstride = (size_t)K * 2;    // bytes per gmem row

    const char* ga[4];
    ga[0] = (const char*)Ah + (size_t)(brow + prow) * kstride + pp * 16;
    ga[1] = (const char*)Al + (size_t)(brow + prow) * kstride + pp * 16;
    ga[2] = (const char*)Bh + (size_t)(bcol + prow) * kstride + pp * 16;
    ga[3] = (const char*)Bl + (size_t)(bcol + prow) * kstride + pp * 16;
    const uint32_t sdst = sb + (uint32_t)prow * (PITCH * 2) + (uint32_t)pp * 16;

    auto load_chunk = [&](int s, int c) {
        const size_t ko = (size_t)c * 64;    // 32 bf16 cols = 64 bytes
        const uint32_t stg = sdst + s * STAGE_B;
        #pragma unroll
        for (int t = 0; t < 4; t++) {
            const char* g = ga[t] + ko;
            CP_ASYNC16(stg + t * TILE_B,      g);
            CP_ASYNC16(stg + t * TILE_B + 16, g + 16);
        }
    };

    // ---- consumer mapping ----
    const int m0w = (wid & 1) * 64;          // warp rows within CTA tile
    const int n0w = (wid >> 1) * 32;         // warp cols
    const int lr  = lane & 15;               // ldmatrix row lane
    const int lc  = (lane >> 4) * 16;        // ldmatrix 16B col chunk

    float acc[4][4][4];
    #pragma unroll
    for (int i = 0; i < 4; i++)
        #pragma unroll
        for (int j = 0; j < 4; j++)
            #pragma unroll
            for (int q = 0; q < 4; q++) acc[i][j][q] = 0.0f;

    const int NC = K >> 5;
    load_chunk(0, 0);
    CP_COMMIT();

    for (int c = 0; c < NC; c++) {
        const int s = c & 1;
        if (c + 1 < NC) { load_chunk(s ^ 1, c + 1); CP_COMMIT(); CP_WAIT1(); }
        else            { CP_WAIT0(); }
        __syncthreads();

        const uint32_t stg = sb + s * STAGE_B;
        const uint32_t sAh = stg;
        const uint32_t sAl = stg + TILE_B;
        const uint32_t sBh = stg + 2 * TILE_B;
        const uint32_t sBl = stg + 3 * TILE_B;

        #pragma unroll
        for (int kb = 0; kb < 2; kb++) {
            const uint32_t kofs = kb * 32 + lc;
            uint32_t ah[4][4], al[4][4], bh[4][2], bl[4][2];
            #pragma unroll
            for (int mi = 0; mi < 4; mi++) {
                const uint32_t ro = (uint32_t)(m0w + mi * 16 + lr) * (PITCH * 2) + kofs;
                ldsm4(ah[mi], sAh + ro);
                ldsm4(al[mi], sAl + ro);
            }
            #pragma unroll
            for (int g2 = 0; g2 < 2; g2++) {
                const uint32_t ro = (uint32_t)(n0w + g2 * 16 + lr) * (PITCH * 2) + kofs;
                uint32_t rh[4], rl[4];
                ldsm4(rh, sBh + ro);
                ldsm4(rl, sBl + ro);
                bh[2*g2][0] = rh[0]; bh[2*g2][1] = rh[2];
                bh[2*g2+1][0] = rh[1]; bh[2*g2+1][1] = rh[3];
                bl[2*g2][0] = rl[0]; bl[2*g2][1] = rl[2];
                bl[2*g2+1][0] = rl[1]; bl[2*g2+1][1] = rl[3];
            }
            #pragma unroll
            for (int mi = 0; mi < 4; mi++)
                #pragma unroll
                for (int ni = 0; ni < 4; ni++) {
                    mma16816(acc[mi][ni], ah[mi], bh[ni]);
                    mma16816(acc[mi][ni], ah[mi], bl[ni]);
                    mma16816(acc[mi][ni], al[mi], bh[ni]);
                }
        }
        __syncthreads();
    }

    // ---- epilogue: mma D layout -> gmem ----
    const int tr  = lane >> 2;               // row within m16 half
    const int tc2 = (lane & 3) * 2;          // col pair within n8
    #pragma unroll
    for (int mi = 0; mi < 4; mi++) {
        #pragma unroll
        for (int ni = 0; ni < 4; ni++) {
            const int col = bcol + n0w + ni * 8 + tc2;
            #pragma unroll
            for (int hf = 0; hf < 2; hf++) {
                const int row = brow + m0w + mi * 16 + tr + hf * 8;
                float v0 = acc[mi][ni][hf * 2];
                float v1 = acc[mi][ni][hf * 2 + 1];
                if (EPI == 0) {
                    *(float2*)(C + (size_t)row * N + col) = make_float2(v0, v1);
                } else if (EPI == 1) {
                    const float2 bb = *(const float2*)(bias + col);
                    const float2 rr = *(const float2*)(res + (size_t)row * N + col);
                    *(float2*)(C + (size_t)row * N + col) =
                        make_float2(v0 + bb.x + rr.x, v1 + bb.y + rr.y);
                } else {
                    const float2 bb = *(const float2*)(bias + col);
                    float g0 = gelu_exact(v0 + bb.x);
                    float g1 = gelu_exact(v1 + bb.y);
                    unsigned short h0, l0, h1, l1;
                    bf16_split(g0, h0, l0);
                    bf16_split(g1, h1, l1);
                    *(uint32_t*)(Ch + (size_t)row * N + col) =
                        (uint32_t)h0 | ((uint32_t)h1 << 16);
                    *(uint32_t*)(Cl + (size_t)row * N + col) =
                        (uint32_t)l0 | ((uint32_t)l1 << 16);
                }
            }
        }
    }
}

// ---------------- Flash attention (fp32, online softmax) -> bf16 split -------
__global__ void __launch_bounds__(128)
flash_kernel(const float* __restrict__ qkv, const int* __restrict__ mask,
             unsigned short* __restrict__ oh, unsigned short* __restrict__ ol)
{
    __shared__ __align__(16) float Ks[64][64];
    __shared__ __align__(16) float Vs[64][64];
    __shared__ unsigned char   Ms[128][68];

    const int bh = blockIdx.y;
    const int b  = bh >> 4;
    const int h  = bh & 15;
    const int q0 = blockIdx.x * 128;
    const int tid = threadIdx.x;
    const int qrow = q0 + tid;
    const float scale = 0.125f;

    float q[64];
    const float* qp = qkv + (size_t)(b * SEQ + qrow) * (3 * INNER) + h * DHEAD;
    #pragma unroll
    for (int d = 0; d < 64; d += 4) {
        float4 t = *(const float4*)(qp + d);
        q[d] = t.x * scale; q[d+1] = t.y * scale;
        q[d+2] = t.z * scale; q[d+3] = t.w * scale;
    }

    float o[64];
    #pragma unroll
    for (int d = 0; d < 64; d++) o[d] = 0.0f;
    float m = -INFINITY, l = 0.0f;

    const int* mrow = mask + ((size_t)b * SEQ + qrow) * SEQ;

    for (int kt = 0; kt < SEQ; kt += 64) {
        {
            const int r = tid >> 1;
            const int c = (tid & 1) * 32;
            const float* kp = qkv + (size_t)(b * SEQ + kt + r) * (3 * INNER)
                              + INNER + h * DHEAD + c;
            const float* vp = kp + INNER;
            #pragma unroll
            for (int j = 0; j < 32; j += 4) {
                *(float4*)&Ks[r][c + j] = *(const float4*)(kp + j);
                *(float4*)&Vs[r][c + j] = *(const float4*)(vp + j);
            }
        }
        {
            const int* mp = mrow + kt;
            #pragma unroll
            for (int j = 0; j < 64; j += 4) {
                int4 mm = *(const int4*)(mp + j);
                Ms[tid][j]     = (unsigned char)mm.x;
                Ms[tid][j + 1] = (unsigned char)mm.y;
                Ms[tid][j + 2] = (unsigned char)mm.z;
                Ms[tid][j + 3] = (unsigned char)mm.w;
            }
        }
        __syncthreads();

        #pragma unroll 1
        for (int kk = 0; kk < 64; kk++) {
            float s0 = 0.f, s1 = 0.f, s2 = 0.f, s3 = 0.f;
            #pragma unroll
            for (int d = 0; d < 64; d += 4) {
                float4 kv = *(const float4*)&Ks[kk][d];
                s0 += q[d]     * kv.x;
                s1 += q[d + 1] * kv.y;
                s2 += q[d + 2] * kv.z;
                s3 += q[d + 3] * kv.w;
            }
            float s = (s0 + s1) + (s2 + s3);
            if (Ms[tid][kk] == 0) s = -1e9f;

            float p;
            if (s > m) {
                float c = __expf(m - s);
                l *= c;
                #pragma unroll
                for (int d = 0; d < 64; d++) o[d] *= c;
                m = s;
                p = 1.0f;
            } else {
                p = __expf(s - m);
            }
            l += p;
            #pragma unroll
            for (int d = 0; d < 64; d += 4) {
                float4 vv = *(const float4*)&Vs[kk][d];
                o[d]     += p * vv.x;
                o[d + 1] += p * vv.y;
                o[d + 2] += p * vv.z;
                o[d + 3] += p * vv.w;
            }
        }
        __syncthreads();
    }

    const float inv = 1.0f / l;
    unsigned short* hp = oh + (size_t)(b * SEQ + qrow) * INNER + h * DHEAD;
    unsigned short* lp = ol + (size_t)(b * SEQ + qrow) * INNER + h * DHEAD;
    #pragma unroll
    for (int d0 = 0; d0 < 64; d0 += 8) {
        uint32_t hw[4], lw[4];
        #pragma unroll
        for (int j = 0; j < 4; j++) {
            float v0 = o[d0 + 2*j]     * inv;
            float v1 = o[d0 + 2*j + 1] * inv;
            unsigned short h0, l0, h1, l1;
            bf16_split(v0, h0, l0);
            bf16_split(v1, h1, l1);
            hw[j] = (uint32_t)h0 | ((uint32_t)h1 << 16);
            lw[j] = (uint32_t)l0 | ((uint32_t)l1 << 16);
        }
        *(uint4*)(hp + d0) = make_uint4(hw[0], hw[1], hw[2], hw[3]);
        *(uint4*)(lp + d0) = make_uint4(lw[0], lw[1], lw[2], lw[3]);
    }
}

// ---------------- host orchestration ----------------------------------------
extern "C" void kernel_launch(void* const* d_in, const int* in_sizes, int n_in,
                              void* d_out, int out_size)
{
    (void)in_sizes; (void)n_in; (void)out_size;
    const float* x_in  = (const float*)d_in[0];
    const int*   mask  = (const int*)  d_in[1];
    const float* ln1_g = (const float*)d_in[2];
    const float* ln1_b = (const float*)d_in[3];
    const float* qkv_w = (const float*)d_in[4];
    const float* out_w = (const float*)d_in[5];
    const float* out_b = (const float*)d_in[6];
    const float* ln2_g = (const float*)d_in[7];
    const float* ln2_b = (const float*)d_in[8];
    const float* ff1_w = (const float*)d_in[9];
    const float* ff1_b = (const float*)d_in[10];
    const float* ff2_w = (const float*)d_in[11];
    const float* ff2_b = (const float*)d_in[12];

    cudaFuncSetAttribute(mma_gemm<0>, cudaFuncAttributeMaxDynamicSharedMemorySize, GSMEM_B);
    cudaFuncSetAttribute(mma_gemm<1>, cudaFuncAttributeMaxDynamicSharedMemorySize, GSMEM_B);
    cudaFuncSetAttribute(mma_gemm<2>, cudaFuncAttributeMaxDynamicSharedMemorySize, GSMEM_B);

    float *p_qkv, *p_x;
    __nv_bfloat16 *p_ah, *p_al, *p_fh, *p_fl;
    __nv_bfloat16 *pwqh, *pwql, *pwoh, *pwol, *pw1h, *pw1l, *pw2h, *pw2l;
    cudaGetSymbolAddress((void**)&p_qkv, g_qkv);
    cudaGetSymbolAddress((void**)&p_x,   g_x);
    cudaGetSymbolAddress((void**)&p_ah,  g_ah);
    cudaGetSymbolAddress((void**)&p_al,  g_al);
    cudaGetSymbolAddress((void**)&p_fh,  g_fh);
    cudaGetSymbolAddress((void**)&p_fl,  g_fl);
    cudaGetSymbolAddress((void**)&pwqh,  w_qkv_h);
    cudaGetSymbolAddress((void**)&pwql,  w_qkv_l);
    cudaGetSymbolAddress((void**)&pwoh,  w_out_h);
    cudaGetSymbolAddress((void**)&pwol,  w_out_l);
    cudaGetSymbolAddress((void**)&pw1h,  w_ff1_h);
    cudaGetSymbolAddress((void**)&pw1l,  w_ff1_l);
    cudaGetSymbolAddress((void**)&pw2h,  w_ff2_h);
    cudaGetSymbolAddress((void**)&pw2l,  w_ff2_l);

    // ---- per-call weight transpose + split ----
    const dim3 cb(32, 8);
    for (int l = 0; l < DEPTH; l++) {
        wconv_kernel<<<dim3(3*INNER/32, DIMV/32), cb>>>(
            qkv_w + (size_t)l * DIMV * 3*INNER,
            pwqh + (size_t)l * 3*INNER * DIMV, pwql + (size_t)l * 3*INNER * DIMV,
            DIMV, 3*INNER);
        wconv_kernel<<<dim3(DIMV/32, INNER/32), cb>>>(
            out_w + (size_t)l * INNER * DIMV,
            pwoh + (size_t)l * DIMV * INNER, pwol + (size_t)l * DIMV * INNER,
            INNER, DIMV);
        wconv_kernel<<<dim3(MLPV/32, DIMV/32), cb>>>(
            ff1_w + (size_t)l * DIMV * MLPV,
            pw1h + (size_t)l * MLPV * DIMV, pw1l + (size_t)l * MLPV * DIMV,
            DIMV, MLPV);
        wconv_kernel<<<dim3(DIMV/32, MLPV/32), cb>>>(
            ff2_w + (size_t)l * MLPV * DIMV,
            pw2h + (size_t)l * DIMV * MLPV, pw2l + (size_t)l * DIMV * MLPV,
            MLPV, DIMV);
    }

    for (int l = 0; l < DEPTH; l++) {
        const float* xsrc = (l == 0) ? x_in : p_x;

        // h = LN1(x) -> bf16 split
        ln_kernel<<<ROWS, 256>>>(xsrc, ln1_g + l * DIMV, ln1_b + l * DIMV,
                                 (unsigned short*)p_ah, (unsigned short*)p_al);

        // qkv = h @ qkv_w[l]  (fp32 out for attention)
        mma_gemm<0><<<dim3(3*INNER/128, ROWS/128), 256, GSMEM_B>>>(
            p_ah, p_al,
            pwqh + (size_t)l * 3*INNER * DIMV, pwql + (size_t)l * 3*INNER * DIMV,
            p_qkv, nullptr, nullptr, nullptr, nullptr, 3*INNER, DIMV);

        // o = attention(q,k,v,mask) -> bf16 split
        flash_kernel<<<dim3(SEQ/128, BATCH*HEADS), 128>>>(
            p_qkv, mask, (unsigned short*)p_ah, (unsigned short*)p_al);

        // x = o @ out_w[l] + out_b[l] + x
        mma_gemm<1><<<dim3(DIMV/128, ROWS/128), 256, GSMEM_B>>>(
            p_ah, p_al,
            pwoh + (size_t)l * DIMV * INNER, pwol + (size_t)l * DIMV * INNER,
            p_x, out_b + l * DIMV, xsrc, nullptr, nullptr, DIMV, INNER);

        // h = LN2(x) -> bf16 split
        ln_kernel<<<ROWS, 256>>>(p_x, ln2_g + l * DIMV, ln2_b + l * DIMV,
                                 (unsigned short*)p_ah, (unsigned short*)p_al);

        // ffh = gelu(h @ ff1_w[l] + ff1_b[l]) -> bf16 split
        mma_gemm<2><<<dim3(MLPV/128, ROWS/128), 256, GSMEM_B>>>(
            p_ah, p_al,
            pw1h + (size_t)l * MLPV * DIMV, pw1l + (size_t)l * MLPV * DIMV,
            nullptr, ff1_b + l * MLPV, nullptr,
            (unsigned short*)p_fh, (unsigned short*)p_fl, MLPV, DIMV);

        // x = ffh @ ff2_w[l] + ff2_b[l] + x   (last layer writes d_out)
        float* xdst = (l == DEPTH - 1) ? (float*)d_out : p_x;
        mma_gemm<1><<<dim3(DIMV/128, ROWS/128), 256, GSMEM_B>>>(
            p_fh, p_fl,
            pw2h + (size_t)l * DIMV * MLPV, pw2l + (size_t)l * DIMV * MLPV,
            xdst, ff2_b + l * DIMV, p_x, nullptr, nullptr, DIMV, MLPV);
    }
}